// round 1
// baseline (speedup 1.0000x reference)
#include <cuda_runtime.h>
#include <cstdint>

#define BB 4
#define SS 2048
#define HH 16
#define DD 72
#define HID 1152
#define EPSF 1e-6f

// Scratch (device globals — no allocation allowed)
__device__ float g_q[BB * SS * HID];
__device__ float g_k[BB * SS * HID];
__device__ float g_v[BB * SS * HID];
__device__ float g_att[BB * SS * HID];

// ---------------------------------------------------------------------------
// SGEMM: C[M,N] = A[M,K] @ W[N,K]^T   (both operands K-contiguous, row-major)
// 128x128 block tile, K-step 8, 256 threads, 8x8 per-thread microtile.
// ---------------------------------------------------------------------------
__global__ __launch_bounds__(256) void sgemm_tn(const float* __restrict__ A,
                                                const float* __restrict__ W,
                                                float* __restrict__ C,
                                                int M, int N, int K) {
    __shared__ float As[8][128];
    __shared__ float Bs[8][128];
    const int bm = blockIdx.y * 128;
    const int bn = blockIdx.x * 128;
    const int tid = threadIdx.x;

    const int lrow = tid >> 1;          // 0..127
    const int lcol = (tid & 1) << 2;    // 0 or 4
    const float* Ap = A + (size_t)(bm + lrow) * K + lcol;
    const float* Wp = W + (size_t)(bn + lrow) * K + lcol;

    const int tx = (tid & 15) << 3;     // 0..120 step 8 (N dir)
    const int ty = (tid >> 4) << 3;     // 0..120 step 8 (M dir)

    float acc[8][8];
#pragma unroll
    for (int i = 0; i < 8; i++)
#pragma unroll
        for (int j = 0; j < 8; j++) acc[i][j] = 0.f;

    for (int k0 = 0; k0 < K; k0 += 8) {
        float4 a4 = *(const float4*)(Ap + k0);
        float4 b4 = *(const float4*)(Wp + k0);
        __syncthreads();
        As[lcol + 0][lrow] = a4.x; As[lcol + 1][lrow] = a4.y;
        As[lcol + 2][lrow] = a4.z; As[lcol + 3][lrow] = a4.w;
        Bs[lcol + 0][lrow] = b4.x; Bs[lcol + 1][lrow] = b4.y;
        Bs[lcol + 2][lrow] = b4.z; Bs[lcol + 3][lrow] = b4.w;
        __syncthreads();
#pragma unroll
        for (int kk = 0; kk < 8; kk++) {
            float ar[8], br[8];
#pragma unroll
            for (int i = 0; i < 8; i++) ar[i] = As[kk][ty + i];
#pragma unroll
            for (int j = 0; j < 8; j++) br[j] = Bs[kk][tx + j];
#pragma unroll
            for (int i = 0; i < 8; i++)
#pragma unroll
                for (int j = 0; j < 8; j++) acc[i][j] += ar[i] * br[j];
        }
    }

#pragma unroll
    for (int i = 0; i < 8; i++) {
        float* Crow = C + (size_t)(bm + ty + i) * N + bn + tx;
#pragma unroll
        for (int j = 0; j < 8; j += 4) {
            float4 v;
            v.x = acc[i][j]; v.y = acc[i][j + 1];
            v.z = acc[i][j + 2]; v.w = acc[i][j + 3];
            *(float4*)(Crow + j) = v;
        }
    }
}

// ---------------------------------------------------------------------------
// Per-(b,s,h) RMS-norm (+weight) and 2D-RoPE for q,k; plain v-norm for v.
// Layout stays [B,S,H,D] (in place). One warp per row; 8 warps per block.
// ---------------------------------------------------------------------------
__global__ __launch_bounds__(256) void norm_rope(const float* __restrict__ cosp,
                                                 const float* __restrict__ sinp,
                                                 const float* __restrict__ qw,
                                                 const float* __restrict__ kw) {
    __shared__ float sh[8][80];
    const int warp = threadIdx.x >> 5;
    const int lane = threadIdx.x & 31;
    const int r = blockIdx.x * 8 + warp;      // r = (b*S+s)*H + h
    const int bs = r / HH;                    // b*S+s
    const float* cp = cosp + (size_t)bs * DD;
    const float* sp = sinp + (size_t)bs * DD;
    const size_t off = (size_t)r * DD;

    const int d0 = lane, d1 = lane + 32, d2 = lane + 64;
    const bool has2 = (lane < 8);

#pragma unroll
    for (int t = 0; t < 2; t++) {
        float* base = (t == 0 ? g_q : g_k) + off;
        const float* w = (t == 0 ? qw : kw);
        float x0 = base[d0];
        float x1 = base[d1];
        float x2 = has2 ? base[d2] : 0.f;
        float ss = x0 * x0 + x1 * x1 + x2 * x2;
#pragma unroll
        for (int o = 16; o; o >>= 1) ss += __shfl_xor_sync(0xffffffffu, ss, o);
        float inv = rsqrtf(ss * (1.f / DD) + EPSF);
        sh[warp][d0] = x0 * inv * w[d0];
        sh[warp][d1] = x1 * inv * w[d1];
        if (has2) sh[warp][d2] = x2 * inv * w[d2];
        __syncwarp();
        // rope2d: x_rot[d] = (d%36 < 18) ? -x[d+18] : x[d-18]
        int ds[3] = {d0, d1, d2};
        int nd = has2 ? 3 : 2;
        for (int ii = 0; ii < nd; ii++) {
            int d = ds[ii];
            int dm = d % 36;
            float rot = (dm < 18) ? -sh[warp][d + 18] : sh[warp][d - 18];
            base[d] = sh[warp][d] * cp[d] + rot * sp[d];
        }
        __syncwarp();
    }

    {   // v: normalize only, no weight, no rope
        float* base = g_v + off;
        float x0 = base[d0];
        float x1 = base[d1];
        float x2 = has2 ? base[d2] : 0.f;
        float ss = x0 * x0 + x1 * x1 + x2 * x2;
#pragma unroll
        for (int o = 16; o; o >>= 1) ss += __shfl_xor_sync(0xffffffffu, ss, o);
        float inv = rsqrtf(ss * (1.f / DD) + EPSF);
        base[d0] = x0 * inv;
        base[d1] = x1 * inv;
        if (has2) base[d2] = x2 * inv;
    }
}

// ---------------------------------------------------------------------------
// Flash attention (fp32, online softmax). One thread per Q row.
// Block: 64 threads (64 Q rows); K/V tiles of 32 rows in shared.
// All shared reads in the hot loops are warp-uniform broadcasts.
// ---------------------------------------------------------------------------
#define FBM 64
#define FBN 32

__global__ __launch_bounds__(64) void flash_attn() {
    __shared__ float Ks[FBN * DD];
    __shared__ float Vs[FBN * DD];
    __shared__ float sc[FBM][FBN + 1];   // +1 pad: conflict-free column writes

    const int tid = threadIdx.x;
    const int bh = blockIdx.y;
    const int b = bh / HH, h = bh % HH;
    const int m = blockIdx.x * FBM + tid;

    const float* qrow = g_q + ((size_t)(b * SS + m) * HH + h) * DD;
    float qr[DD], o[DD];
#pragma unroll
    for (int d = 0; d < DD; d++) { qr[d] = qrow[d]; o[d] = 0.f; }
    float mval = -1e30f, l = 0.f;

    for (int n0 = 0; n0 < SS; n0 += FBN) {
        __syncthreads();   // previous tile fully consumed before overwrite
        // load K,V tiles as float4 (rows are 72 floats = 18 float4, 16B aligned)
        for (int idx = tid; idx < FBN * 18; idx += FBM) {
            int row = idx / 18, c = idx % 18;
            size_t gb = ((size_t)(b * SS + n0 + row) * HH + h) * DD + (size_t)c * 4;
            ((float4*)Ks)[idx] = *(const float4*)(g_k + gb);
            ((float4*)Vs)[idx] = *(const float4*)(g_v + gb);
        }
        __syncthreads();

        float tmax = -1e30f;
        for (int j = 0; j < FBN; j++) {
            const float* kr = Ks + j * DD;
            float s0 = 0.f, s1 = 0.f, s2 = 0.f, s3 = 0.f;
#pragma unroll
            for (int d = 0; d < DD; d += 4) {
                s0 += qr[d + 0] * kr[d + 0];
                s1 += qr[d + 1] * kr[d + 1];
                s2 += qr[d + 2] * kr[d + 2];
                s3 += qr[d + 3] * kr[d + 3];
            }
            float s = (s0 + s1) + (s2 + s3);
            sc[tid][j] = s;
            tmax = fmaxf(tmax, s);
        }

        float mnew = fmaxf(mval, tmax);
        float alpha = __expf(mval - mnew);
        l *= alpha;
#pragma unroll
        for (int d = 0; d < DD; d++) o[d] *= alpha;

        for (int j = 0; j < FBN; j++) {
            float p = __expf(sc[tid][j] - mnew);
            l += p;
            const float* vr = Vs + j * DD;
#pragma unroll
            for (int d = 0; d < DD; d++) o[d] += p * vr[d];
        }
        mval = mnew;
    }

    float invl = 1.f / l;
    float* orow = g_att + ((size_t)(b * SS + m) * HH + h) * DD;
#pragma unroll
    for (int d = 0; d < DD; d++) orow[d] = o[d] * invl;
}

// ---------------------------------------------------------------------------
// Launch
// ---------------------------------------------------------------------------
extern "C" void kernel_launch(void* const* d_in, const int* in_sizes, int n_in,
                              void* d_out, int out_size) {
    const float* hidden = (const float*)d_in[0];
    const float* cosp   = (const float*)d_in[1];
    const float* sinp   = (const float*)d_in[2];
    const float* Wq     = (const float*)d_in[3];
    const float* Wk     = (const float*)d_in[4];
    const float* Wv     = (const float*)d_in[5];
    const float* Wo     = (const float*)d_in[6];
    const float* qw     = (const float*)d_in[7];
    const float* kw     = (const float*)d_in[8];
    float* out = (float*)d_out;

    float *q_p, *k_p, *v_p, *att_p;
    cudaGetSymbolAddress((void**)&q_p,   g_q);
    cudaGetSymbolAddress((void**)&k_p,   g_k);
    cudaGetSymbolAddress((void**)&v_p,   g_v);
    cudaGetSymbolAddress((void**)&att_p, g_att);

    const int M = BB * SS;          // 8192
    dim3 gg(HID / 128, M / 128);    // (9, 64)

    sgemm_tn<<<gg, 256>>>(hidden, Wq, q_p, M, HID, HID);
    sgemm_tn<<<gg, 256>>>(hidden, Wk, k_p, M, HID, HID);
    sgemm_tn<<<gg, 256>>>(hidden, Wv, v_p, M, HID, HID);

    norm_rope<<<(BB * SS * HH) / 8, 256>>>(cosp, sinp, qw, kw);

    flash_attn<<<dim3(SS / FBM, BB * HH), FBM>>>();

    sgemm_tn<<<gg, 256>>>(att_p, Wo, out, M, HID, HID);
}

// round 2
// speedup vs baseline: 1.0882x; 1.0882x over previous
#include <cuda_runtime.h>
#include <cstdint>

#define BB 4
#define SS 2048
#define HH 16
#define DD 72
#define HID 1152
#define EPSF 1e-6f

// Scratch (device globals — no allocation allowed)
__device__ float g_q[BB * SS * HID];
__device__ float g_k[BB * SS * HID];
__device__ float g_v[BB * SS * HID];
__device__ float g_att[BB * SS * HID];

// ---------------------------------------------------------------------------
// tf32 helpers
// ---------------------------------------------------------------------------
__device__ __forceinline__ float to_tf32(float x) {
    uint32_t u;
    asm("cvt.rna.tf32.f32 %0, %1;" : "=r"(u) : "f"(x));
    return __uint_as_float(u);
}

__device__ __forceinline__ void mma_tf32(float* c, const uint32_t* a, const uint32_t* b) {
    asm volatile(
        "mma.sync.aligned.m16n8k8.row.col.f32.tf32.tf32.f32 "
        "{%0,%1,%2,%3}, {%4,%5,%6,%7}, {%8,%9}, {%0,%1,%2,%3};"
        : "+f"(c[0]), "+f"(c[1]), "+f"(c[2]), "+f"(c[3])
        : "r"(a[0]), "r"(a[1]), "r"(a[2]), "r"(a[3]), "r"(b[0]), "r"(b[1]));
}

// ---------------------------------------------------------------------------
// tf32 tensor-core GEMM: C[M,N] = A[M,K] @ W[N,K]^T  (row-major, K-contig)
// 128x128 block tile, BK=16, 256 threads, 8 warps in 2(M)x4(N), warp=64x32.
// SPLIT=1: A,W split into tf32 hi+lo; acc += Ah*Wh + Ah*Wl + Al*Wh (fp32-acc)
// Smem holds fragments pre-permuted: A frag = 1 LDS.128, B frag = 1 LDS.64.
// ---------------------------------------------------------------------------
template <int SPLIT>
__global__ __launch_bounds__(256) void gemm_tf32(const float* __restrict__ A,
                                                 const float* __restrict__ W,
                                                 float* __restrict__ C,
                                                 int M, int N, int K) {
    // per k8-chunk: A = 8 mtiles * 128 floats; B = 16 ntiles * 64 floats
    __shared__ float As[2048], Bs[2048];
    __shared__ float AsL[SPLIT ? 2048 : 1], BsL[SPLIT ? 2048 : 1];

    const int tid = threadIdx.x;
    const int lane = tid & 31;
    const int warp = tid >> 5;
    const int bm = blockIdx.y * 128;
    const int bn = blockIdx.x * 128;
    const int wm = (warp >> 2) * 64;   // warp M offset in block tile
    const int wn = (warp & 3) * 32;    // warp N offset

    const int lrow = tid >> 1;           // 0..127 (tile row for global loads)
    const int lkg = (tid & 1) * 8;       // 0 or 8 (k group)
    const float* Ap = A + (size_t)(bm + lrow) * K + lkg;
    const float* Wp = W + (size_t)(bn + lrow) * K + lkg;

    float acc[4][4][4];
#pragma unroll
    for (int i = 0; i < 4; i++)
#pragma unroll
        for (int j = 0; j < 4; j++)
#pragma unroll
            for (int r = 0; r < 4; r++) acc[i][j][r] = 0.f;

    // smem store index for A element (row rr in 0..127, k in 0..15)
    auto a_off = [](int r, int k) {
        int c = k >> 3, kk = k & 7, mt = r >> 4, rr = r & 15;
        int ln = ((rr & 7) << 2) | (kk & 3);
        int rg = (rr >> 3) | ((kk >> 2) << 1);
        return ((c << 3) + mt) * 128 + ln * 4 + rg;
    };
    auto b_off = [](int n, int k) {
        int c = k >> 3, kk = k & 7, nt = n >> 3, nn = n & 7;
        int ln = (nn << 2) | (kk & 3);
        int rg = kk >> 2;
        return ((c << 4) + nt) * 64 + ln * 2 + rg;
    };

    for (int k0 = 0; k0 < K; k0 += 16) {
        float av[8], wv[8];
        *(float4*)(av)     = *(const float4*)(Ap + k0);
        *(float4*)(av + 4) = *(const float4*)(Ap + k0 + 4);
        *(float4*)(wv)     = *(const float4*)(Wp + k0);
        *(float4*)(wv + 4) = *(const float4*)(Wp + k0 + 4);

        __syncthreads();
#pragma unroll
        for (int j = 0; j < 8; j++) {
            int kA = lkg + j;
            int oa = a_off(lrow, kA);
            int ob = b_off(lrow, kA);
            float ah = to_tf32(av[j]);
            float wh = to_tf32(wv[j]);
            As[oa] = ah;
            Bs[ob] = wh;
            if (SPLIT) {
                AsL[oa] = av[j] - ah;
                BsL[ob] = wv[j] - wh;
            }
        }
        __syncthreads();

#pragma unroll
        for (int c = 0; c < 2; c++) {
            uint32_t ah[4][4], bh[4][2];
            uint32_t al[4][4], bl[4][2];
#pragma unroll
            for (int i = 0; i < 4; i++) {
                int mt = (wm >> 4) + i;             // m-tile index 0..7
                int base = ((c << 3) + mt) * 128 + lane * 4;
                float4 v = *(const float4*)(As + base);
                ah[i][0] = __float_as_uint(v.x); ah[i][1] = __float_as_uint(v.y);
                ah[i][2] = __float_as_uint(v.z); ah[i][3] = __float_as_uint(v.w);
                if (SPLIT) {
                    float4 vl = *(const float4*)(AsL + base);
                    al[i][0] = __float_as_uint(vl.x); al[i][1] = __float_as_uint(vl.y);
                    al[i][2] = __float_as_uint(vl.z); al[i][3] = __float_as_uint(vl.w);
                }
            }
#pragma unroll
            for (int j = 0; j < 4; j++) {
                int nt = (wn >> 3) + j;             // n-tile index 0..15
                int base = ((c << 4) + nt) * 64 + lane * 2;
                float2 v = *(const float2*)(Bs + base);
                bh[j][0] = __float_as_uint(v.x); bh[j][1] = __float_as_uint(v.y);
                if (SPLIT) {
                    float2 vl = *(const float2*)(BsL + base);
                    bl[j][0] = __float_as_uint(vl.x); bl[j][1] = __float_as_uint(vl.y);
                }
            }
#pragma unroll
            for (int i = 0; i < 4; i++)
#pragma unroll
                for (int j = 0; j < 4; j++) {
                    mma_tf32(acc[i][j], ah[i], bh[j]);
                    if (SPLIT) {
                        mma_tf32(acc[i][j], ah[i], bl[j]);
                        mma_tf32(acc[i][j], al[i], bh[j]);
                    }
                }
        }
    }

    // epilogue: c0/c1 at (row, 2c),(row,2c+1); c2/c3 at row+8
#pragma unroll
    for (int i = 0; i < 4; i++) {
#pragma unroll
        for (int j = 0; j < 4; j++) {
            int m0 = bm + wm + i * 16 + (lane >> 2);
            int n0 = bn + wn + j * 8 + (lane & 3) * 2;
            float2 lo, hi2;
            lo.x = acc[i][j][0]; lo.y = acc[i][j][1];
            hi2.x = acc[i][j][2]; hi2.y = acc[i][j][3];
            *(float2*)(C + (size_t)m0 * N + n0) = lo;
            *(float2*)(C + (size_t)(m0 + 8) * N + n0) = hi2;
        }
    }
}

// ---------------------------------------------------------------------------
// Per-(b,s,h) RMS-norm (+weight) and 2D-RoPE for q,k; plain v-norm for v.
// ---------------------------------------------------------------------------
__global__ __launch_bounds__(256) void norm_rope(const float* __restrict__ cosp,
                                                 const float* __restrict__ sinp,
                                                 const float* __restrict__ qw,
                                                 const float* __restrict__ kw) {
    __shared__ float sh[8][80];
    const int warp = threadIdx.x >> 5;
    const int lane = threadIdx.x & 31;
    const int r = blockIdx.x * 8 + warp;
    const int bs = r / HH;
    const float* cp = cosp + (size_t)bs * DD;
    const float* sp = sinp + (size_t)bs * DD;
    const size_t off = (size_t)r * DD;

    const int d0 = lane, d1 = lane + 32, d2 = lane + 64;
    const bool has2 = (lane < 8);

#pragma unroll
    for (int t = 0; t < 2; t++) {
        float* base = (t == 0 ? g_q : g_k) + off;
        const float* w = (t == 0 ? qw : kw);
        float x0 = base[d0];
        float x1 = base[d1];
        float x2 = has2 ? base[d2] : 0.f;
        float ss = x0 * x0 + x1 * x1 + x2 * x2;
#pragma unroll
        for (int o = 16; o; o >>= 1) ss += __shfl_xor_sync(0xffffffffu, ss, o);
        float inv = rsqrtf(ss * (1.f / DD) + EPSF);
        sh[warp][d0] = x0 * inv * w[d0];
        sh[warp][d1] = x1 * inv * w[d1];
        if (has2) sh[warp][d2] = x2 * inv * w[d2];
        __syncwarp();
        int ds[3] = {d0, d1, d2};
        int nd = has2 ? 3 : 2;
        for (int ii = 0; ii < nd; ii++) {
            int d = ds[ii];
            int dm = d % 36;
            float rot = (dm < 18) ? -sh[warp][d + 18] : sh[warp][d - 18];
            base[d] = sh[warp][d] * cp[d] + rot * sp[d];
        }
        __syncwarp();
    }

    {
        float* base = g_v + off;
        float x0 = base[d0];
        float x1 = base[d1];
        float x2 = has2 ? base[d2] : 0.f;
        float ss = x0 * x0 + x1 * x1 + x2 * x2;
#pragma unroll
        for (int o = 16; o; o >>= 1) ss += __shfl_xor_sync(0xffffffffu, ss, o);
        float inv = rsqrtf(ss * (1.f / DD) + EPSF);
        base[d0] = x0 * inv;
        base[d1] = x1 * inv;
        if (has2) base[d2] = x2 * inv;
    }
}

// ---------------------------------------------------------------------------
// Flash attention (fp32, online softmax). One thread per Q row.
// ---------------------------------------------------------------------------
#define FBM 64
#define FBN 32

__global__ __launch_bounds__(64) void flash_attn() {
    __shared__ float Ks[FBN * DD];
    __shared__ float Vs[FBN * DD];
    __shared__ float sc[FBM][FBN + 1];

    const int tid = threadIdx.x;
    const int bh = blockIdx.y;
    const int b = bh / HH, h = bh % HH;
    const int m = blockIdx.x * FBM + tid;

    const float* qrow = g_q + ((size_t)(b * SS + m) * HH + h) * DD;
    float qr[DD], o[DD];
#pragma unroll
    for (int d = 0; d < DD; d++) { qr[d] = qrow[d]; o[d] = 0.f; }
    float mval = -1e30f, l = 0.f;

    for (int n0 = 0; n0 < SS; n0 += FBN) {
        __syncthreads();
        for (int idx = tid; idx < FBN * 18; idx += FBM) {
            int row = idx / 18, c = idx % 18;
            size_t gb = ((size_t)(b * SS + n0 + row) * HH + h) * DD + (size_t)c * 4;
            ((float4*)Ks)[idx] = *(const float4*)(g_k + gb);
            ((float4*)Vs)[idx] = *(const float4*)(g_v + gb);
        }
        __syncthreads();

        float tmax = -1e30f;
        for (int j = 0; j < FBN; j++) {
            const float* kr = Ks + j * DD;
            float s0 = 0.f, s1 = 0.f, s2 = 0.f, s3 = 0.f;
#pragma unroll
            for (int d = 0; d < DD; d += 4) {
                s0 += qr[d + 0] * kr[d + 0];
                s1 += qr[d + 1] * kr[d + 1];
                s2 += qr[d + 2] * kr[d + 2];
                s3 += qr[d + 3] * kr[d + 3];
            }
            float s = (s0 + s1) + (s2 + s3);
            sc[tid][j] = s;
            tmax = fmaxf(tmax, s);
        }

        float mnew = fmaxf(mval, tmax);
        float alpha = __expf(mval - mnew);
        l *= alpha;
#pragma unroll
        for (int d = 0; d < DD; d++) o[d] *= alpha;

        for (int j = 0; j < FBN; j++) {
            float p = __expf(sc[tid][j] - mnew);
            l += p;
            const float* vr = Vs + j * DD;
#pragma unroll
            for (int d = 0; d < DD; d++) o[d] += p * vr[d];
        }
        mval = mnew;
    }

    float invl = 1.f / l;
    float* orow = g_att + ((size_t)(b * SS + m) * HH + h) * DD;
#pragma unroll
    for (int d = 0; d < DD; d++) orow[d] = o[d] * invl;
}

// ---------------------------------------------------------------------------
// Launch
// ---------------------------------------------------------------------------
extern "C" void kernel_launch(void* const* d_in, const int* in_sizes, int n_in,
                              void* d_out, int out_size) {
    const float* hidden = (const float*)d_in[0];
    const float* cosp   = (const float*)d_in[1];
    const float* sinp   = (const float*)d_in[2];
    const float* Wq     = (const float*)d_in[3];
    const float* Wk     = (const float*)d_in[4];
    const float* Wv     = (const float*)d_in[5];
    const float* Wo     = (const float*)d_in[6];
    const float* qw     = (const float*)d_in[7];
    const float* kw     = (const float*)d_in[8];
    float* out = (float*)d_out;

    float *q_p, *k_p, *v_p, *att_p;
    cudaGetSymbolAddress((void**)&q_p,   g_q);
    cudaGetSymbolAddress((void**)&k_p,   g_k);
    cudaGetSymbolAddress((void**)&v_p,   g_v);
    cudaGetSymbolAddress((void**)&att_p, g_att);

    const int M = BB * SS;          // 8192
    dim3 gg(HID / 128, M / 128);    // (9, 64)

    // Q,K need near-fp32 accuracy (scores feed softmax): split tf32 (3 mma).
    gemm_tf32<1><<<gg, 256>>>(hidden, Wq, q_p, M, HID, HID);
    gemm_tf32<1><<<gg, 256>>>(hidden, Wk, k_p, M, HID, HID);
    // V and Wo enter linearly: single-pass tf32 is plenty.
    gemm_tf32<0><<<gg, 256>>>(hidden, Wv, v_p, M, HID, HID);

    norm_rope<<<(BB * SS * HH) / 8, 256>>>(cosp, sinp, qw, kw);

    flash_attn<<<dim3(SS / FBM, BB * HH), FBM>>>();

    gemm_tf32<0><<<gg, 256>>>(att_p, Wo, out, M, HID, HID);
}

// round 4
// speedup vs baseline: 1.5593x; 1.4329x over previous
#include <cuda_runtime.h>
#include <cstdint>

#define BB 4
#define SS 2048
#define HH 16
#define DD 72
#define HID 1152
#define EPSF 1e-6f
#define LOG2E 1.4426950408889634f

// Scratch (device globals — no allocation allowed)
__device__ float g_q[BB * SS * HID];
__device__ float g_k[BB * SS * HID];
__device__ float g_v[BB * SS * HID];
__device__ float g_att[BB * SS * HID];

// ---------------------------------------------------------------------------
// tf32 helpers
// ---------------------------------------------------------------------------
__device__ __forceinline__ float to_tf32(float x) {
    uint32_t u;
    asm("cvt.rna.tf32.f32 %0, %1;" : "=r"(u) : "f"(x));
    return __uint_as_float(u);
}

__device__ __forceinline__ void mma_tf32(float* c, const uint32_t* a, const uint32_t* b) {
    asm volatile(
        "mma.sync.aligned.m16n8k8.row.col.f32.tf32.tf32.f32 "
        "{%0,%1,%2,%3}, {%4,%5,%6,%7}, {%8,%9}, {%0,%1,%2,%3};"
        : "+f"(c[0]), "+f"(c[1]), "+f"(c[2]), "+f"(c[3])
        : "r"(a[0]), "r"(a[1]), "r"(a[2]), "r"(a[3]), "r"(b[0]), "r"(b[1]));
}

// exp2 via degree-5 FFMA polynomial (rel err ~2.4e-6). Avoids the MUFU pipe.
__device__ __forceinline__ float exp2_poly(float t) {
    t = fmaxf(t, -126.0f);
    float r = rintf(t);
    float f = t - r;
    float p = 1.3337167e-3f;
    p = fmaf(p, f, 9.6181291e-3f);
    p = fmaf(p, f, 5.5504109e-2f);
    p = fmaf(p, f, 2.4022651e-1f);
    p = fmaf(p, f, 6.9314718e-1f);
    p = fmaf(p, f, 1.0f);
    return __int_as_float(__float_as_int(p) + (((int)r) << 23));
}

// ---------------------------------------------------------------------------
// tf32 tensor-core GEMM: C[M,N] = A[M,K] @ W[N,K]^T (unchanged)
// ---------------------------------------------------------------------------
template <int SPLIT>
__global__ __launch_bounds__(256) void gemm_tf32(const float* __restrict__ A,
                                                 const float* __restrict__ W,
                                                 float* __restrict__ C,
                                                 int M, int N, int K) {
    __shared__ float As[2048], Bs[2048];
    __shared__ float AsL[SPLIT ? 2048 : 1], BsL[SPLIT ? 2048 : 1];

    const int tid = threadIdx.x;
    const int lane = tid & 31;
    const int warp = tid >> 5;
    const int bm = blockIdx.y * 128;
    const int bn = blockIdx.x * 128;
    const int wm = (warp >> 2) * 64;
    const int wn = (warp & 3) * 32;

    const int lrow = tid >> 1;
    const int lkg = (tid & 1) * 8;
    const float* Ap = A + (size_t)(bm + lrow) * K + lkg;
    const float* Wp = W + (size_t)(bn + lrow) * K + lkg;

    float acc[4][4][4];
#pragma unroll
    for (int i = 0; i < 4; i++)
#pragma unroll
        for (int j = 0; j < 4; j++)
#pragma unroll
            for (int r = 0; r < 4; r++) acc[i][j][r] = 0.f;

    auto a_off = [](int r, int k) {
        int c = k >> 3, kk = k & 7, mt = r >> 4, rr = r & 15;
        int ln = ((rr & 7) << 2) | (kk & 3);
        int rg = (rr >> 3) | ((kk >> 2) << 1);
        return ((c << 3) + mt) * 128 + ln * 4 + rg;
    };
    auto b_off = [](int n, int k) {
        int c = k >> 3, kk = k & 7, nt = n >> 3, nn = n & 7;
        int ln = (nn << 2) | (kk & 3);
        int rg = kk >> 2;
        return ((c << 4) + nt) * 64 + ln * 2 + rg;
    };

    for (int k0 = 0; k0 < K; k0 += 16) {
        float av[8], wv[8];
        *(float4*)(av)     = *(const float4*)(Ap + k0);
        *(float4*)(av + 4) = *(const float4*)(Ap + k0 + 4);
        *(float4*)(wv)     = *(const float4*)(Wp + k0);
        *(float4*)(wv + 4) = *(const float4*)(Wp + k0 + 4);

        __syncthreads();
#pragma unroll
        for (int j = 0; j < 8; j++) {
            int kA = lkg + j;
            int oa = a_off(lrow, kA);
            int ob = b_off(lrow, kA);
            float ah = to_tf32(av[j]);
            float wh = to_tf32(wv[j]);
            As[oa] = ah;
            Bs[ob] = wh;
            if (SPLIT) {
                AsL[oa] = av[j] - ah;
                BsL[ob] = wv[j] - wh;
            }
        }
        __syncthreads();

#pragma unroll
        for (int c = 0; c < 2; c++) {
            uint32_t ah[4][4], bh[4][2];
            uint32_t al[4][4], bl[4][2];
#pragma unroll
            for (int i = 0; i < 4; i++) {
                int mt = (wm >> 4) + i;
                int base = ((c << 3) + mt) * 128 + lane * 4;
                float4 v = *(const float4*)(As + base);
                ah[i][0] = __float_as_uint(v.x); ah[i][1] = __float_as_uint(v.y);
                ah[i][2] = __float_as_uint(v.z); ah[i][3] = __float_as_uint(v.w);
                if (SPLIT) {
                    float4 vl = *(const float4*)(AsL + base);
                    al[i][0] = __float_as_uint(vl.x); al[i][1] = __float_as_uint(vl.y);
                    al[i][2] = __float_as_uint(vl.z); al[i][3] = __float_as_uint(vl.w);
                }
            }
#pragma unroll
            for (int j = 0; j < 4; j++) {
                int nt = (wn >> 3) + j;
                int base = ((c << 4) + nt) * 64 + lane * 2;
                float2 v = *(const float2*)(Bs + base);
                bh[j][0] = __float_as_uint(v.x); bh[j][1] = __float_as_uint(v.y);
                if (SPLIT) {
                    float2 vl = *(const float2*)(BsL + base);
                    bl[j][0] = __float_as_uint(vl.x); bl[j][1] = __float_as_uint(vl.y);
                }
            }
#pragma unroll
            for (int i = 0; i < 4; i++)
#pragma unroll
                for (int j = 0; j < 4; j++) {
                    mma_tf32(acc[i][j], ah[i], bh[j]);
                    if (SPLIT) {
                        mma_tf32(acc[i][j], ah[i], bl[j]);
                        mma_tf32(acc[i][j], al[i], bh[j]);
                    }
                }
        }
    }

#pragma unroll
    for (int i = 0; i < 4; i++) {
#pragma unroll
        for (int j = 0; j < 4; j++) {
            int m0 = bm + wm + i * 16 + (lane >> 2);
            int n0 = bn + wn + j * 8 + (lane & 3) * 2;
            float2 lo, hi2;
            lo.x = acc[i][j][0]; lo.y = acc[i][j][1];
            hi2.x = acc[i][j][2]; hi2.y = acc[i][j][3];
            *(float2*)(C + (size_t)m0 * N + n0) = lo;
            *(float2*)(C + (size_t)(m0 + 8) * N + n0) = hi2;
        }
    }
}

// ---------------------------------------------------------------------------
// Per-(b,s,h) RMS-norm (+weight) and 2D-RoPE for q,k; plain v-norm for v.
// ---------------------------------------------------------------------------
__global__ __launch_bounds__(256) void norm_rope(const float* __restrict__ cosp,
                                                 const float* __restrict__ sinp,
                                                 const float* __restrict__ qw,
                                                 const float* __restrict__ kw) {
    __shared__ float sh[8][80];
    const int warp = threadIdx.x >> 5;
    const int lane = threadIdx.x & 31;
    const int r = blockIdx.x * 8 + warp;
    const int bs = r / HH;
    const float* cp = cosp + (size_t)bs * DD;
    const float* sp = sinp + (size_t)bs * DD;
    const size_t off = (size_t)r * DD;

    const int d0 = lane, d1 = lane + 32, d2 = lane + 64;
    const bool has2 = (lane < 8);

#pragma unroll
    for (int t = 0; t < 2; t++) {
        float* base = (t == 0 ? g_q : g_k) + off;
        const float* w = (t == 0 ? qw : kw);
        float x0 = base[d0];
        float x1 = base[d1];
        float x2 = has2 ? base[d2] : 0.f;
        float ss = x0 * x0 + x1 * x1 + x2 * x2;
#pragma unroll
        for (int o = 16; o; o >>= 1) ss += __shfl_xor_sync(0xffffffffu, ss, o);
        float inv = rsqrtf(ss * (1.f / DD) + EPSF);
        sh[warp][d0] = x0 * inv * w[d0];
        sh[warp][d1] = x1 * inv * w[d1];
        if (has2) sh[warp][d2] = x2 * inv * w[d2];
        __syncwarp();
        int ds[3] = {d0, d1, d2};
        int nd = has2 ? 3 : 2;
        for (int ii = 0; ii < nd; ii++) {
            int d = ds[ii];
            int dm = d % 36;
            float rot = (dm < 18) ? -sh[warp][d + 18] : sh[warp][d - 18];
            base[d] = sh[warp][d] * cp[d] + rot * sp[d];
        }
        __syncwarp();
    }

    {
        float* base = g_v + off;
        float x0 = base[d0];
        float x1 = base[d1];
        float x2 = has2 ? base[d2] : 0.f;
        float ss = x0 * x0 + x1 * x1 + x2 * x2;
#pragma unroll
        for (int o = 16; o; o >>= 1) ss += __shfl_xor_sync(0xffffffffu, ss, o);
        float inv = rsqrtf(ss * (1.f / DD) + EPSF);
        base[d0] = x0 * inv;
        base[d1] = x1 * inv;
        if (has2) base[d2] = x2 * inv;
    }
}

// ---------------------------------------------------------------------------
// MMA flash attention. Block = 128 thr (4 warps), 64 Q rows, 32-key tiles.
// QK^T: split tf32 (3 mma). PV: single tf32. Softmax exp: FFMA polynomial.
// ---------------------------------------------------------------------------
#define AT_BM 64
#define AT_BN 32

__global__ __launch_bounds__(128) void flash_attn_mma() {
    __shared__ float Khs[9 * 4 * 64];         // K hi, fragment-permuted
    __shared__ float Kls[9 * 4 * 64];         // K lo
    __shared__ float Vs[AT_BN * 76];          // V (tf32-rounded), row stride 76
    __shared__ float Ps[4][16 * 36];          // per-warp P patch

    const int tid = threadIdx.x;
    const int lane = tid & 31;
    const int warp = tid >> 5;
    const int q4 = lane & 3;
    const int r8 = lane >> 2;
    const int bh = blockIdx.y;
    const int b = bh >> 4, h = bh & 15;
    const int m0 = blockIdx.x * AT_BM;

    const size_t headoff = (size_t)b * SS * HID + h * DD;

    // ---- load Q fragments (rows r1, r1+8), split hi/lo ----
    uint32_t qh[9][4], ql[9][4];
    const int r1 = m0 + warp * 16 + r8;
    {
        const float* p1 = g_q + headoff + (size_t)r1 * HID;
        const float* p2 = p1 + 8 * HID;
#pragma unroll
        for (int ks = 0; ks < 9; ks++) {
            float v0 = p1[ks * 8 + q4];
            float v1 = p2[ks * 8 + q4];
            float v2 = p1[ks * 8 + q4 + 4];
            float v3 = p2[ks * 8 + q4 + 4];
            float h0 = to_tf32(v0), h1 = to_tf32(v1), h2 = to_tf32(v2), h3 = to_tf32(v3);
            qh[ks][0] = __float_as_uint(h0); qh[ks][1] = __float_as_uint(h1);
            qh[ks][2] = __float_as_uint(h2); qh[ks][3] = __float_as_uint(h3);
            ql[ks][0] = __float_as_uint(to_tf32(v0 - h0));
            ql[ks][1] = __float_as_uint(to_tf32(v1 - h1));
            ql[ks][2] = __float_as_uint(to_tf32(v2 - h2));
            ql[ks][3] = __float_as_uint(to_tf32(v3 - h3));
        }
    }

    float o[9][4];
#pragma unroll
    for (int dt = 0; dt < 9; dt++)
#pragma unroll
        for (int e = 0; e < 4; e++) o[dt][e] = 0.f;
    float m0r = -1e30f, m1r = -1e30f;
    float l0r = 0.f, l1r = 0.f;

    for (int n0 = 0; n0 < SS; n0 += AT_BN) {
        __syncthreads();
        // ---- cooperative K/V tile load (+ tf32 rounding / hi-lo split) ----
        // FIX: 576 float4s / 128 threads = 4.5 iterations -> idx-strided loop
        {
            const float* kbase = g_k + headoff + (size_t)n0 * HID;
            const float* vbase = g_v + headoff + (size_t)n0 * HID;
            for (int idx = tid; idx < AT_BN * 18; idx += 128) {
                int row = idx / 18, c = idx % 18;
                const float4 kv = *(const float4*)(kbase + (size_t)row * HID + c * 4);
                const float4 vv = *(const float4*)(vbase + (size_t)row * HID + c * 4);
                int nt = row >> 3, nn = row & 7;
                int base = ((c >> 1) * 4 + nt) * 64 + (c & 1);
                float kj[4] = {kv.x, kv.y, kv.z, kv.w};
#pragma unroll
                for (int j = 0; j < 4; j++) {
                    float hi = to_tf32(kj[j]);
                    int a = base + (nn * 4 + j) * 2;
                    Khs[a] = hi;
                    Kls[a] = to_tf32(kj[j] - hi);
                }
                float* vd = Vs + row * 76 + c * 4;
                vd[0] = to_tf32(vv.x); vd[1] = to_tf32(vv.y);
                vd[2] = to_tf32(vv.z); vd[3] = to_tf32(vv.w);
            }
        }
        __syncthreads();

        // ---- scores: S = Q K^T (split tf32) ----
        float accs[4][4];
#pragma unroll
        for (int nt = 0; nt < 4; nt++)
#pragma unroll
            for (int e = 0; e < 4; e++) accs[nt][e] = 0.f;

#pragma unroll
        for (int ks = 0; ks < 9; ks++) {
#pragma unroll
            for (int nt = 0; nt < 4; nt++) {
                int fb = (ks * 4 + nt) * 64 + lane * 2;
                float2 vh = *(const float2*)(Khs + fb);
                float2 vl = *(const float2*)(Kls + fb);
                uint32_t bh2[2] = {__float_as_uint(vh.x), __float_as_uint(vh.y)};
                uint32_t bl2[2] = {__float_as_uint(vl.x), __float_as_uint(vl.y)};
                mma_tf32(accs[nt], qh[ks], bh2);
                mma_tf32(accs[nt], ql[ks], bh2);
                mma_tf32(accs[nt], qh[ks], bl2);
            }
        }

        // ---- online softmax ----
        float t0 = -1e30f, t1 = -1e30f;
#pragma unroll
        for (int nt = 0; nt < 4; nt++) {
            t0 = fmaxf(t0, fmaxf(accs[nt][0], accs[nt][1]));
            t1 = fmaxf(t1, fmaxf(accs[nt][2], accs[nt][3]));
        }
        t0 = fmaxf(t0, __shfl_xor_sync(0xffffffffu, t0, 1));
        t0 = fmaxf(t0, __shfl_xor_sync(0xffffffffu, t0, 2));
        t1 = fmaxf(t1, __shfl_xor_sync(0xffffffffu, t1, 1));
        t1 = fmaxf(t1, __shfl_xor_sync(0xffffffffu, t1, 2));
        float mn0 = fmaxf(m0r, t0), mn1 = fmaxf(m1r, t1);
        float al0 = exp2_poly((m0r - mn0) * LOG2E);
        float al1 = exp2_poly((m1r - mn1) * LOG2E);
        l0r *= al0; l1r *= al1;
#pragma unroll
        for (int dt = 0; dt < 9; dt++) {
            o[dt][0] *= al0; o[dt][1] *= al0;
            o[dt][2] *= al1; o[dt][3] *= al1;
        }

        float* pw = Ps[warp];
        float ls0 = 0.f, ls1 = 0.f;
#pragma unroll
        for (int nt = 0; nt < 4; nt++) {
            float p0 = exp2_poly((accs[nt][0] - mn0) * LOG2E);
            float p1 = exp2_poly((accs[nt][1] - mn0) * LOG2E);
            float p2 = exp2_poly((accs[nt][2] - mn1) * LOG2E);
            float p3 = exp2_poly((accs[nt][3] - mn1) * LOG2E);
            ls0 += p0 + p1; ls1 += p2 + p3;
            pw[r8 * 36 + nt * 8 + 2 * q4]           = to_tf32(p0);
            pw[r8 * 36 + nt * 8 + 2 * q4 + 1]       = to_tf32(p1);
            pw[(r8 + 8) * 36 + nt * 8 + 2 * q4]     = to_tf32(p2);
            pw[(r8 + 8) * 36 + nt * 8 + 2 * q4 + 1] = to_tf32(p3);
        }
        l0r += ls0; l1r += ls1;
        m0r = mn0; m1r = mn1;
        __syncwarp();

        // ---- P A-fragments from smem ----
        uint32_t pa[4][4];
#pragma unroll
        for (int k2 = 0; k2 < 4; k2++) {
            pa[k2][0] = __float_as_uint(pw[r8 * 36 + k2 * 8 + q4]);
            pa[k2][1] = __float_as_uint(pw[(r8 + 8) * 36 + k2 * 8 + q4]);
            pa[k2][2] = __float_as_uint(pw[r8 * 36 + k2 * 8 + q4 + 4]);
            pa[k2][3] = __float_as_uint(pw[(r8 + 8) * 36 + k2 * 8 + q4 + 4]);
        }

        // ---- O += P V ----
#pragma unroll
        for (int k2 = 0; k2 < 4; k2++) {
#pragma unroll
            for (int dt = 0; dt < 9; dt++) {
                uint32_t vb[2];
                vb[0] = __float_as_uint(Vs[(k2 * 8 + q4) * 76 + dt * 8 + r8]);
                vb[1] = __float_as_uint(Vs[(k2 * 8 + 4 + q4) * 76 + dt * 8 + r8]);
                mma_tf32(o[dt], pa[k2], vb);
            }
        }
    }

    // ---- epilogue ----
    l0r += __shfl_xor_sync(0xffffffffu, l0r, 1);
    l0r += __shfl_xor_sync(0xffffffffu, l0r, 2);
    l1r += __shfl_xor_sync(0xffffffffu, l1r, 1);
    l1r += __shfl_xor_sync(0xffffffffu, l1r, 2);
    float i0 = 1.f / l0r, i1 = 1.f / l1r;

    float* o1 = g_att + headoff + (size_t)r1 * HID;
    float* o2 = o1 + 8 * HID;
#pragma unroll
    for (int dt = 0; dt < 9; dt++) {
        float2 w1, w2;
        w1.x = o[dt][0] * i0; w1.y = o[dt][1] * i0;
        w2.x = o[dt][2] * i1; w2.y = o[dt][3] * i1;
        *(float2*)(o1 + dt * 8 + 2 * q4) = w1;
        *(float2*)(o2 + dt * 8 + 2 * q4) = w2;
    }
}

// ---------------------------------------------------------------------------
// Launch
// ---------------------------------------------------------------------------
extern "C" void kernel_launch(void* const* d_in, const int* in_sizes, int n_in,
                              void* d_out, int out_size) {
    const float* hidden = (const float*)d_in[0];
    const float* cosp   = (const float*)d_in[1];
    const float* sinp   = (const float*)d_in[2];
    const float* Wq     = (const float*)d_in[3];
    const float* Wk     = (const float*)d_in[4];
    const float* Wv     = (const float*)d_in[5];
    const float* Wo     = (const float*)d_in[6];
    const float* qw     = (const float*)d_in[7];
    const float* kw     = (const float*)d_in[8];
    float* out = (float*)d_out;

    float *q_p, *k_p, *v_p, *att_p;
    cudaGetSymbolAddress((void**)&q_p,   g_q);
    cudaGetSymbolAddress((void**)&k_p,   g_k);
    cudaGetSymbolAddress((void**)&v_p,   g_v);
    cudaGetSymbolAddress((void**)&att_p, g_att);

    const int M = BB * SS;          // 8192
    dim3 gg(HID / 128, M / 128);    // (9, 64)

    gemm_tf32<1><<<gg, 256>>>(hidden, Wq, q_p, M, HID, HID);
    gemm_tf32<1><<<gg, 256>>>(hidden, Wk, k_p, M, HID, HID);
    gemm_tf32<0><<<gg, 256>>>(hidden, Wv, v_p, M, HID, HID);

    norm_rope<<<(BB * SS * HH) / 8, 256>>>(cosp, sinp, qw, kw);

    flash_attn_mma<<<dim3(SS / AT_BM, BB * HH), 128>>>();

    gemm_tf32<0><<<gg, 256>>>(att_p, Wo, out, M, HID, HID);
}